// round 13
// baseline (speedup 1.0000x reference)
#include <cuda_runtime.h>
#include <cuda_bf16.h>
#include <cstdint>

// BS=64, G=64, L=100, D=64. NG=4096 groups.
// softmax shift-invariance: V_last/V_avg/b cancel => attn = softmax_l(seqs[l].(W2@p)).
// lens, W1, W3, b unused.
// SINGLE warp-specialized kernel: 128 CTAs x 512 threads, 32 groups/CTA.
//  warps 0-7: two 128-thread attn squads (16 groups each, sequential, desynced)
//  warps 8-15: MLP consumer: weights smem-staged via cp.async; processes
//              4-row batches through all 3 layers as attn flags them ready.

#define NG 4096
#define L  100
#define D  64
#define GB 32                    // groups per CTA

typedef unsigned long long u64;

// ---------------- smem layout (bytes) ----------------
#define OF_WQ    0               // 32768   Wq   [64][128] f
#define OF_WL0   32768           // 65536   Wl0  [128][128] f
#define OF_WL1   98304           // 65536   Wl1  [128][128] f
#define OF_W2S   163840          // 16640   w2s  [64][65] f
#define OF_PS    180480          // 256     p
#define OF_QS    180736          // 256     q
#define OF_ASH   180992          // 832(+)  attn_sh [2][104] f
#define OF_RED   181888          // 64      red  [2][4] f
#define OF_P4    181952          // 2048    part4 [2][4][16][4] f
#define OF_XR    184000          // 8192    xrows [32][64] f
#define OF_FLAGS 192192          // 128     flags[32]
#define OF_P     192320          // 16384   P    [8][4][64] u64
#define OF_HD    208704          // 4096    hdup [4][128] u64
#define OF_H0P   212800          // 2048    h0pair [4][64] u64
#define SMEM_TOTAL 215040

// ---------------- helpers ----------------
__device__ __forceinline__ void cp16(unsigned int s_addr, const void* g) {
    asm volatile("cp.async.cg.shared.global [%0], [%1], 16;\n" :: "r"(s_addr), "l"(g));
}
#define CP_COMMIT() asm volatile("cp.async.commit_group;\n" ::: "memory")
#define CP_WAIT(n)  asm volatile("cp.async.wait_group %0;\n" :: "n"(n) : "memory")
#define BARX(id, cnt) asm volatile("bar.sync %0, %1;" :: "r"(id), "r"(cnt) : "memory")

__device__ __forceinline__ u64 pk2(float v) {
    u64 r; asm("mov.b64 %0, {%1, %1};" : "=l"(r) : "f"(v)); return r;
}
__device__ __forceinline__ void fma2(u64& d, u64 a, u64 b) {
    asm("fma.rn.f32x2 %0, %1, %2, %0;" : "+l"(d) : "l"(a), "l"(b));
}
__device__ __forceinline__ void add2(u64& d, u64 a) {
    asm("add.rn.f32x2 %0, %0, %1;" : "+l"(d) : "l"(a));
}
__device__ __forceinline__ float2 unpk(u64 v) {
    float2 r; asm("mov.b64 {%0, %1}, %2;" : "=f"(r.x), "=f"(r.y) : "l"(v)); return r;
}
__device__ __forceinline__ u64 pkpair(float lo, float hi) {
    u64 r; asm("mov.b64 %0, {%1, %2};" : "=l"(r) : "f"(lo), "f"(hi)); return r;
}

// ---------------------------------------------------------------------------
__global__ __launch_bounds__(512) void fused_kernel(
    const float* __restrict__ seqs, const float* __restrict__ W2,
    const float* __restrict__ p,    const float* __restrict__ Wq,
    const float* __restrict__ Wl0,  const float* __restrict__ bl0,
    const float* __restrict__ Wl1,  const float* __restrict__ bl1,
    float* __restrict__ out)
{
    extern __shared__ char sm[];
    float* wqs    = (float*)(sm + OF_WQ);
    float* wl0s   = (float*)(sm + OF_WL0);
    float* wl1s   = (float*)(sm + OF_WL1);
    float* w2s    = (float*)(sm + OF_W2S);
    float* ps     = (float*)(sm + OF_PS);
    float* q_s    = (float*)(sm + OF_QS);
    float* ash    = (float*)(sm + OF_ASH);     // [2][104]
    float* red    = (float*)(sm + OF_RED);     // [2][4]
    float* part4  = (float*)(sm + OF_P4);      // [2][4][16][4]
    float* xrows  = (float*)(sm + OF_XR);      // [32][64]
    volatile int* flags = (volatile int*)(sm + OF_FLAGS);
    u64*   P      = (u64*)(sm + OF_P);         // [8][4][64]
    u64*   hdup   = (u64*)(sm + OF_HD);        // [4][128]
    u64*   h0pair = (u64*)(sm + OF_H0P);       // [4][64]

    const int tid    = threadIdx.x;
    const int g_base = blockIdx.x * GB;
    const unsigned int sb = (unsigned int)__cvta_generic_to_shared(sm);

    if (tid < GB) ((int*)(sm + OF_FLAGS))[tid] = 0;
    __syncthreads();

    if (tid < 256) {
        // ======================= ATTENTION ROLE =======================
        const int s    = tid >> 7;         // squad
        const int t    = tid & 127;
        const int w    = t >> 5;
        const int lane = t & 31;
        const int c4   = t & 15;
        const int grp  = t >> 4;
        const int bar  = 3 + s;            // squad barrier id

        // ---- stage W2 (coalesced) + p ----
#pragma unroll
        for (int i = 0; i < 4; ++i) {
            int idx = tid + i * 256;
            float4 wv = __ldg((const float4*)W2 + idx);
            int row = idx >> 4, c = idx & 15;
            float* dst = &w2s[row * 65 + c * 4];
            dst[0] = wv.x; dst[1] = wv.y; dst[2] = wv.z; dst[3] = wv.w;
        }
        if (tid >= 64 && tid < 128) ps[tid - 64] = __ldg(p + tid - 64);
        BARX(1, 256);

        if (tid < D) {
            float acc = 0.f;
            const float* row = &w2s[tid * 65];
#pragma unroll 16
            for (int e = 0; e < D; ++e) acc += row[e] * ps[e];
            q_s[tid] = acc;
        }
        BARX(1, 256);

        const float4 q4 = *(const float4*)&q_s[c4 * 4];

        for (int it = 0; it < GB / 2; ++it) {
            const int gl = s + 2 * it;          // local group
            const int g  = g_base + gl;

            // ---- load tile into registers ----
            const float4* src = (const float4*)(seqs + (size_t)g * (L * D));
            float4 r[13];
#pragma unroll
            for (int k = 0; k < 13; ++k) {
                int idx = t + k * 128;
                if (idx < L * (D / 4)) r[k] = __ldg(src + idx);
                else                   r[k] = make_float4(0.f, 0.f, 0.f, 0.f);
            }

            // ---- emb: segmented shfl dot ----
#pragma unroll
            for (int k = 0; k < 13; ++k) {
                float v = r[k].x * q4.x + r[k].y * q4.y + r[k].z * q4.z + r[k].w * q4.w;
                v += __shfl_xor_sync(0xffffffffu, v, 1);
                v += __shfl_xor_sync(0xffffffffu, v, 2);
                v += __shfl_xor_sync(0xffffffffu, v, 4);
                v += __shfl_xor_sync(0xffffffffu, v, 8);
                int row = grp + 8 * k;
                if (c4 == 0 && row < L) ash[s * 104 + row] = v;
            }
            BARX(bar, 128);

            // ---- softmax over L=100 ----
            float v = (t < L) ? ash[s * 104 + t] : -1e30f;
            float m = v;
#pragma unroll
            for (int o = 16; o > 0; o >>= 1) m = fmaxf(m, __shfl_xor_sync(0xffffffffu, m, o));
            if (lane == 0) red[s * 4 + w] = m;
            BARX(bar, 128);
            float vmax = fmaxf(fmaxf(red[s * 4 + 0], red[s * 4 + 1]),
                               fmaxf(red[s * 4 + 2], red[s * 4 + 3]));
            BARX(bar, 128);

            float e = (t < L) ? __expf(v - vmax) : 0.f;
            float sv = e;
#pragma unroll
            for (int o = 16; o > 0; o >>= 1) sv += __shfl_xor_sync(0xffffffffu, sv, o);
            if (lane == 0) red[s * 4 + w] = sv;
            BARX(bar, 128);
            float inv = 1.f / (red[s * 4 + 0] + red[s * 4 + 1] +
                               red[s * 4 + 2] + red[s * 4 + 3]);
            if (t < L) ash[s * 104 + t] = e * inv;
            else if (t < 104) ash[s * 104 + t] = 0.f;
            BARX(bar, 128);

            // ---- pooling ----
            float4 p4 = make_float4(0.f, 0.f, 0.f, 0.f);
#pragma unroll
            for (int k = 0; k < 13; ++k) {
                float a = ash[s * 104 + grp + 8 * k];
                p4.x += a * r[k].x; p4.y += a * r[k].y;
                p4.z += a * r[k].z; p4.w += a * r[k].w;
            }
            p4.x += __shfl_xor_sync(0xffffffffu, p4.x, 16);
            p4.y += __shfl_xor_sync(0xffffffffu, p4.y, 16);
            p4.z += __shfl_xor_sync(0xffffffffu, p4.z, 16);
            p4.w += __shfl_xor_sync(0xffffffffu, p4.w, 16);
            if (lane < 16)
                *(float4*)&part4[((s * 4 + w) * 16 + lane) * 4] = p4;
            BARX(bar, 128);
            if (t < D) {
                int ci = t >> 2, comp = t & 3;
                float sum = part4[((s * 4 + 0) * 16 + ci) * 4 + comp]
                          + part4[((s * 4 + 1) * 16 + ci) * 4 + comp]
                          + part4[((s * 4 + 2) * 16 + ci) * 4 + comp]
                          + part4[((s * 4 + 3) * 16 + ci) * 4 + comp];
                xrows[gl * 64 + t] = sum;
            }
            BARX(bar, 128);                    // xrows complete (BAR drains STS)
            if (t == 0) {
                __threadfence_block();
                flags[gl] = 1;
            }
        }
    } else {
        // ========================= MLP ROLE =========================
        const int mt   = tid - 256;
        const int wr   = mt >> 5;          // 0..7 (K-split slice)
        const int lane = mt & 31;
        const int rr_r = mt >> 6;          // reduce: row 0..3
        const int cp   = mt & 63;          // reduce: u64 col-pair 0..63

        // ---- stage all weights: C1=Wq, C2=Wl0, C3=Wl1 ----
#pragma unroll
        for (int i = 0; i < 8; ++i) {
            int idx = mt + i * 256;                       // 2048 f4
            cp16(sb + OF_WQ + idx * 16, (const float4*)Wq + idx);
        }
        CP_COMMIT();
#pragma unroll
        for (int i = 0; i < 16; ++i) {
            int idx = mt + i * 256;                       // 4096 f4
            cp16(sb + OF_WL0 + idx * 16, (const float4*)Wl0 + idx);
        }
        CP_COMMIT();
#pragma unroll
        for (int i = 0; i < 16; ++i) {
            int idx = mt + i * 256;
            cp16(sb + OF_WL1 + idx * 16, (const float4*)Wl1 + idx);
        }
        CP_COMMIT();

        for (int b = 0; b < GB / 4; ++b) {
            // ---- wait for 4 rows ----
            while (!(flags[4 * b] & flags[4 * b + 1] &
                     flags[4 * b + 2] & flags[4 * b + 3]))
                __nanosleep(128);
            __threadfence_block();

            u64 a[4][2];

            // ======== stage 1: h0 = X @ Wq (K=64, slice 8/warp) ========
            CP_WAIT(2);
            {
#pragma unroll
                for (int i = 0; i < 4; ++i) { a[i][0] = 0ull; a[i][1] = 0ull; }
                const int d0 = wr * 8;
#pragma unroll
                for (int i = 0; i < 8; ++i) {
                    const int d = d0 + i;
                    float4 wv = *(const float4*)&wqs[d * 128 + lane * 4];
                    u64 w0 = *(const u64*)&wv.x, w1 = *(const u64*)&wv.z;
#pragma unroll
                    for (int rr = 0; rr < 4; ++rr) {
                        u64 xd = pk2(xrows[(4 * b + rr) * 64 + d]);
                        fma2(a[rr][0], xd, w0);
                        fma2(a[rr][1], xd, w1);
                    }
                }
#pragma unroll
                for (int rr = 0; rr < 4; ++rr)
                    *(ulonglong2*)&P[(wr * 4 + rr) * 64 + lane * 2] =
                        make_ulonglong2(a[rr][0], a[rr][1]);
            }
            BARX(2, 256);
            {   // reduce 8 partials -> h0pair + hdup
                u64 s0 = P[rr_r * 64 + cp];
#pragma unroll
                for (int kh = 1; kh < 8; ++kh)
                    add2(s0, P[(kh * 4 + rr_r) * 64 + cp]);
                h0pair[rr_r * 64 + cp] = s0;
                float2 f = unpk(s0);
                hdup[rr_r * 128 + 2 * cp]     = pk2(f.x);
                hdup[rr_r * 128 + 2 * cp + 1] = pk2(f.y);
            }
            BARX(2, 256);

            // ======== stage 2: h1 = relu(h0 @ Wl0 + bl0) (K=128) ========
            CP_WAIT(1);
            {
#pragma unroll
                for (int i = 0; i < 4; ++i) { a[i][0] = 0ull; a[i][1] = 0ull; }
                const int d0 = wr * 16;
#pragma unroll
                for (int i = 0; i < 16; ++i) {
                    const int d = d0 + i;
                    float4 wv = *(const float4*)&wl0s[d * 128 + lane * 4];
                    u64 w0 = *(const u64*)&wv.x, w1 = *(const u64*)&wv.z;
#pragma unroll
                    for (int rr = 0; rr < 4; ++rr) {
                        u64 xd = hdup[rr * 128 + d];
                        fma2(a[rr][0], xd, w0);
                        fma2(a[rr][1], xd, w1);
                    }
                }
#pragma unroll
                for (int rr = 0; rr < 4; ++rr)
                    *(ulonglong2*)&P[(wr * 4 + rr) * 64 + lane * 2] =
                        make_ulonglong2(a[rr][0], a[rr][1]);
            }
            BARX(2, 256);
            {
                u64 s0 = P[rr_r * 64 + cp];
#pragma unroll
                for (int kh = 1; kh < 8; ++kh)
                    add2(s0, P[(kh * 4 + rr_r) * 64 + cp]);
                add2(s0, *(const u64*)&bl0[2 * cp]);
                float2 f = unpk(s0);
                f.x = fmaxf(f.x, 0.f); f.y = fmaxf(f.y, 0.f);
                hdup[rr_r * 128 + 2 * cp]     = pk2(f.x);
                hdup[rr_r * 128 + 2 * cp + 1] = pk2(f.y);
            }
            BARX(2, 256);

            // ======== stage 3: out = h0 + relu(h1 @ Wl1 + bl1) ========
            CP_WAIT(0);
            {
#pragma unroll
                for (int i = 0; i < 4; ++i) { a[i][0] = 0ull; a[i][1] = 0ull; }
                const int d0 = wr * 16;
#pragma unroll
                for (int i = 0; i < 16; ++i) {
                    const int d = d0 + i;
                    float4 wv = *(const float4*)&wl1s[d * 128 + lane * 4];
                    u64 w0 = *(const u64*)&wv.x, w1 = *(const u64*)&wv.z;
#pragma unroll
                    for (int rr = 0; rr < 4; ++rr) {
                        u64 xd = hdup[rr * 128 + d];
                        fma2(a[rr][0], xd, w0);
                        fma2(a[rr][1], xd, w1);
                    }
                }
#pragma unroll
                for (int rr = 0; rr < 4; ++rr)
                    *(ulonglong2*)&P[(wr * 4 + rr) * 64 + lane * 2] =
                        make_ulonglong2(a[rr][0], a[rr][1]);
            }
            BARX(2, 256);
            {
                u64 s0 = P[rr_r * 64 + cp];
#pragma unroll
                for (int kh = 1; kh < 8; ++kh)
                    add2(s0, P[(kh * 4 + rr_r) * 64 + cp]);
                add2(s0, *(const u64*)&bl1[2 * cp]);
                float2 f = unpk(s0);
                u64 o = pkpair(fmaxf(f.x, 0.f), fmaxf(f.y, 0.f));
                add2(o, h0pair[rr_r * 64 + cp]);
                *(u64*)&out[(size_t)(g_base + 4 * b + rr_r) * 128 + 2 * cp] = o;
            }
            BARX(2, 256);          // P/hdup free for next batch
        }
    }
}

// ---------------------------------------------------------------------------
extern "C" void kernel_launch(void* const* d_in, const int* in_sizes, int n_in,
                              void* d_out, int out_size) {
    const float* seqs = (const float*)d_in[0];
    // d_in[1]=lens, d_in[2]=W1, d_in[4]=W3, d_in[5]=b : unused (cancel in softmax)
    const float* W2   = (const float*)d_in[3];
    const float* p    = (const float*)d_in[6];
    const float* Wq   = (const float*)d_in[7];
    const float* Wl0  = (const float*)d_in[8];
    const float* bl0  = (const float*)d_in[9];
    const float* Wl1  = (const float*)d_in[10];
    const float* bl1  = (const float*)d_in[11];
    float* out = (float*)d_out;

    static bool init_done = false;
    if (!init_done) {
        cudaFuncSetAttribute(fused_kernel,
                             cudaFuncAttributeMaxDynamicSharedMemorySize, SMEM_TOTAL);
        init_done = true;
    }

    fused_kernel<<<NG / GB, 512, SMEM_TOTAL>>>(seqs, W2, p, Wq, Wl0, bl0,
                                               Wl1, bl1, out);
}

// round 15
// speedup vs baseline: 1.4545x; 1.4545x over previous
#include <cuda_runtime.h>
#include <cuda_bf16.h>
#include <cstdint>

// BS=64, G=64, L=100, D=64. NG=4096 groups.
// softmax shift-invariance: V_last/V_avg/b cancel => attn = softmax_l(seqs[l].(W2@p)).
// lens, W1, W3, b unused.
// attn: R6 (20.6us, DRAM-bound). MLP: 1024 threads (32 warps = 8 rowtiles x 4 kh),
// 216KB smem-staged weights; P2 reduction scratch aliases dead wq region.

#define NG   4096
#define L    100
#define D    64

typedef unsigned long long u64;

__device__ float g_weighted[NG * D];

// ---------------------------------------------------------------------------
// helpers
// ---------------------------------------------------------------------------
__device__ __forceinline__ void cp16(unsigned int s_addr, const void* g) {
    asm volatile("cp.async.cg.shared.global [%0], [%1], 16;\n" :: "r"(s_addr), "l"(g));
}
#define CP_COMMIT() asm volatile("cp.async.commit_group;\n" ::: "memory")
#define CP_WAIT(n)  asm volatile("cp.async.wait_group %0;\n" :: "n"(n) : "memory")

__device__ __forceinline__ u64 pk2(float v) {
    u64 r; asm("mov.b64 %0, {%1, %1};" : "=l"(r) : "f"(v)); return r;
}
__device__ __forceinline__ void fma2(u64& d, u64 a, u64 b) {
    asm("fma.rn.f32x2 %0, %1, %2, %0;" : "+l"(d) : "l"(a), "l"(b));
}
__device__ __forceinline__ void add2(u64& d, u64 a) {
    asm("add.rn.f32x2 %0, %0, %1;" : "+l"(d) : "l"(a));
}
__device__ __forceinline__ float2 unpk(u64 v) {
    float2 r; asm("mov.b64 {%0, %1}, %2;" : "=f"(r.x), "=f"(r.y) : "l"(v)); return r;
}

// u64-pair index for a 4-col group starting at c0: pair index = c0/2
__device__ __forceinline__ int lane2(int c0) { return c0 >> 1; }

// ---------------------------------------------------------------------------
// Kernel 1: attention pooling, 2 groups per block, 256 threads. (R6, unchanged)
// ---------------------------------------------------------------------------
__global__ __launch_bounds__(256) void attn_kernel(
    const float* __restrict__ seqs, const float* __restrict__ W2,
    const float* __restrict__ p)
{
    __shared__ float w2s[D * 65];
    __shared__ float ps[D];
    __shared__ float q_s[D];
    __shared__ float attn_sh[2][104];
    __shared__ float red[2][4];
    __shared__ float part4[2][4][16][4];

    const int tid  = threadIdx.x;
    const int half = tid >> 7;
    const int t    = tid & 127;
    const int g    = blockIdx.x * 2 + half;
    const int w    = t >> 5;
    const int lane = t & 31;
    const int c4   = t & 15;
    const int grp  = t >> 4;

    const float4* src = (const float4*)(seqs + (size_t)g * (L * D));
    float4 r[13];
#pragma unroll
    for (int k = 0; k < 13; ++k) {
        int idx = t + k * 128;
        if (idx < L * (D / 4)) r[k] = __ldg(src + idx);
        else                   r[k] = make_float4(0.f, 0.f, 0.f, 0.f);
    }

#pragma unroll
    for (int i = 0; i < 4; ++i) {
        int idx = tid + i * 256;
        float4 wv = __ldg((const float4*)W2 + idx);
        int row = idx >> 4, c = idx & 15;
        float* dst = &w2s[row * 65 + c * 4];
        dst[0] = wv.x; dst[1] = wv.y; dst[2] = wv.z; dst[3] = wv.w;
    }
    if (tid >= 64 && tid < 128) ps[tid - 64] = __ldg(p + tid - 64);
    __syncthreads();

    if (tid < D) {
        float acc = 0.f;
        const float* row = &w2s[tid * 65];
#pragma unroll 16
        for (int e = 0; e < D; ++e) acc += row[e] * ps[e];
        q_s[tid] = acc;
    }
    __syncthreads();

    const float4 q4 = *(const float4*)&q_s[c4 * 4];
#pragma unroll
    for (int k = 0; k < 13; ++k) {
        float v = r[k].x * q4.x + r[k].y * q4.y + r[k].z * q4.z + r[k].w * q4.w;
        v += __shfl_xor_sync(0xffffffffu, v, 1);
        v += __shfl_xor_sync(0xffffffffu, v, 2);
        v += __shfl_xor_sync(0xffffffffu, v, 4);
        v += __shfl_xor_sync(0xffffffffu, v, 8);
        int row = grp + 8 * k;
        if (c4 == 0 && row < L) attn_sh[half][row] = v;
    }
    __syncthreads();

    float v = (t < L) ? attn_sh[half][t] : -1e30f;
    float m = v;
#pragma unroll
    for (int o = 16; o > 0; o >>= 1) m = fmaxf(m, __shfl_xor_sync(0xffffffffu, m, o));
    if (lane == 0) red[half][w] = m;
    __syncthreads();
    float vmax = fmaxf(fmaxf(red[half][0], red[half][1]),
                       fmaxf(red[half][2], red[half][3]));
    __syncthreads();

    float e = (t < L) ? __expf(v - vmax) : 0.f;
    float sv = e;
#pragma unroll
    for (int o = 16; o > 0; o >>= 1) sv += __shfl_xor_sync(0xffffffffu, sv, o);
    if (lane == 0) red[half][w] = sv;
    __syncthreads();
    float inv = 1.f / (red[half][0] + red[half][1] + red[half][2] + red[half][3]);
    if (t < L) attn_sh[half][t] = e * inv;
    else if (t < 104) attn_sh[half][t] = 0.f;
    __syncthreads();

    float4 p4 = make_float4(0.f, 0.f, 0.f, 0.f);
#pragma unroll
    for (int k = 0; k < 13; ++k) {
        float a = attn_sh[half][grp + 8 * k];
        p4.x += a * r[k].x; p4.y += a * r[k].y;
        p4.z += a * r[k].z; p4.w += a * r[k].w;
    }
    p4.x += __shfl_xor_sync(0xffffffffu, p4.x, 16);
    p4.y += __shfl_xor_sync(0xffffffffu, p4.y, 16);
    p4.z += __shfl_xor_sync(0xffffffffu, p4.z, 16);
    p4.w += __shfl_xor_sync(0xffffffffu, p4.w, 16);
    if (lane < 16) *(float4*)&part4[half][w][lane][0] = p4;
    __syncthreads();
    if (t < D) {
        int ci = t >> 2, comp = t & 3;
        float sum = part4[half][0][ci][comp] + part4[half][1][ci][comp]
                  + part4[half][2][ci][comp] + part4[half][3][ci][comp];
        g_weighted[g * D + t] = sum;
    }
}

// ---------------------------------------------------------------------------
// MLP: 128 blocks x 1024 threads, 32 rows/block.
// warp wr (0..31): kh = wr>>3 (K-quarter), rt = wr&7 -> rows [rt*4, +4).
// lane -> cols [lane*4, +4). acc: 4 rows x 2 u64 (f32x2 col-pairs).
// smem (floats): sx[2048] sh0[4096] sh1[4096] P1(u64[32][64])=4096f
//                wq[8192](=P2 u64[2][32][64] after stage1 compute)
//                wl0[16384] wl1[16384]   total 55296 f = 216 KB
// ---------------------------------------------------------------------------
template<int K, bool BIAS, bool RELU, bool RESID, bool GSTORE>
__device__ __forceinline__ void mlp_stage(
    const float* __restrict__ xb, int xs,          // input + stride
    const float* __restrict__ ws,                  // weights [K][128]
    u64* __restrict__ P1, u64* __restrict__ P2,
    const float* __restrict__ bias, const float* __restrict__ resid,
    float* __restrict__ obuf, int grow0,
    int kh, int r0, int c0)
{
    u64 acc[4][2];
#pragma unroll
    for (int i = 0; i < 4; ++i) { acc[i][0] = 0ull; acc[i][1] = 0ull; }

    const int dbase = kh * (K / 4);
#pragma unroll 4
    for (int i = 0; i < K / 4; ++i) {
        const int dd = dbase + i;
        float4 wv = *(const float4*)&ws[dd * 128 + c0];
        u64 w0 = *(const u64*)&wv.x, w1 = *(const u64*)&wv.z;
#pragma unroll
        for (int row = 0; row < 4; ++row) {
            u64 x = pk2(xb[(r0 + row) * xs + dd]);   // warp-uniform broadcast
            fma2(acc[row][0], x, w0);
            fma2(acc[row][1], x, w1);
        }
    }
    __syncthreads();          // all weight (incl. wq-region) reads complete

    if (kh == 2) {
#pragma unroll
        for (int row = 0; row < 4; ++row)
            *(ulonglong2*)&P2[(r0 + row) * 64 + lane2(c0)] =
                make_ulonglong2(acc[row][0], acc[row][1]);
    }
    if (kh == 3) {
#pragma unroll
        for (int row = 0; row < 4; ++row)
            *(ulonglong2*)&P2[(32 + r0 + row) * 64 + lane2(c0)] =
                make_ulonglong2(acc[row][0], acc[row][1]);
    }
    __syncthreads();
    if (kh == 0) {
#pragma unroll
        for (int row = 0; row < 4; ++row) {
            ulonglong2 q = *(ulonglong2*)&P2[(r0 + row) * 64 + lane2(c0)];
            add2(acc[row][0], q.x); add2(acc[row][1], q.y);
        }
    }
    if (kh == 1) {
#pragma unroll
        for (int row = 0; row < 4; ++row) {
            ulonglong2 q = *(ulonglong2*)&P2[(32 + r0 + row) * 64 + lane2(c0)];
            add2(acc[row][0], q.x); add2(acc[row][1], q.y);
            *(ulonglong2*)&P1[(r0 + row) * 64 + lane2(c0)] =
                make_ulonglong2(acc[row][0], acc[row][1]);
        }
    }
    __syncthreads();
    if (kh == 0) {
        u64 bv0 = 0ull, bv1 = 0ull;
        if (BIAS) { bv0 = *(const u64*)&bias[c0]; bv1 = *(const u64*)&bias[c0 + 2]; }
#pragma unroll
        for (int row = 0; row < 4; ++row) {
            ulonglong2 q = *(ulonglong2*)&P1[(r0 + row) * 64 + lane2(c0)];
            add2(acc[row][0], q.x); add2(acc[row][1], q.y);
            if (BIAS) { add2(acc[row][0], bv0); add2(acc[row][1], bv1); }
            float2 a = unpk(acc[row][0]), b = unpk(acc[row][1]);
            if (RELU) {
                a.x = fmaxf(a.x, 0.f); a.y = fmaxf(a.y, 0.f);
                b.x = fmaxf(b.x, 0.f); b.y = fmaxf(b.y, 0.f);
            }
            float4 o = make_float4(a.x, a.y, b.x, b.y);
            if (RESID) {
                const float* rr = &resid[(r0 + row) * 128 + c0];
                o.x += rr[0]; o.y += rr[1]; o.z += rr[2]; o.w += rr[3];
            }
            if (GSTORE)
                *(float4*)&obuf[(size_t)(grow0 + r0 + row) * 128 + c0] = o;
            else
                *(float4*)&obuf[(r0 + row) * 128 + c0] = o;
        }
    }
    __syncthreads();
}

__global__ __launch_bounds__(1024) void mlp_kernel(
    const float* __restrict__ Wq,  const float* __restrict__ Wl0,
    const float* __restrict__ bl0, const float* __restrict__ Wl1,
    const float* __restrict__ bl1, float* __restrict__ out)
{
    extern __shared__ float smem[];
    float* sx  = smem;             // [32][64]
    float* sh0 = smem + 2048;      // [32][128]
    float* sh1 = smem + 6144;      // [32][128]
    u64*   P1  = (u64*)(smem + 10240);   // [32][64]
    float* wq  = smem + 14336;     // [64][128]  (aliased as P2 after stage1)
    u64*   P2  = (u64*)(smem + 14336);   // [2][32][64]
    float* wl0 = smem + 22528;     // [128][128]
    float* wl1 = smem + 38912;     // [128][128]  total 55296 f = 216 KB

    const int t    = threadIdx.x;
    const int row0 = blockIdx.x * 32;
    const unsigned int sb = (unsigned int)__cvta_generic_to_shared(smem);

    // ---- async staging: C1 = sx + wq, C2 = wl0, C3 = wl1 ----
    if (t < 512)
        cp16(sb + t * 16, (const float4*)(g_weighted + (size_t)row0 * D) + t);
#pragma unroll
    for (int i = 0; i < 2; ++i) {
        int idx = t + i * 1024;                             // 2048 f4
        cp16(sb + (14336 + idx * 4) * 4, (const float4*)Wq + idx);
    }
    CP_COMMIT();
#pragma unroll
    for (int i = 0; i < 4; ++i) {
        int idx = t + i * 1024;                             // 4096 f4
        cp16(sb + (22528 + idx * 4) * 4, (const float4*)Wl0 + idx);
    }
    CP_COMMIT();
#pragma unroll
    for (int i = 0; i < 4; ++i) {
        int idx = t + i * 1024;
        cp16(sb + (38912 + idx * 4) * 4, (const float4*)Wl1 + idx);
    }
    CP_COMMIT();

    const int wr = t >> 5;          // warp 0..31
    const int kh = wr >> 3;         // K-quarter
    const int r0 = (wr & 7) * 4;    // rows [r0, r0+4)
    const int c0 = (t & 31) * 4;    // cols [c0, c0+4)

    // ---- stage 1: h0 = X @ Wq (K=64) -> sh0 ----
    CP_WAIT(2);
    __syncthreads();
    mlp_stage<64, false, false, false, false>(
        sx, 64, wq, P1, P2, nullptr, nullptr, sh0, 0, kh, r0, c0);

    // ---- stage 2: h1 = relu(h0 @ Wl0 + bl0) -> sh1 ----
    CP_WAIT(1);
    __syncthreads();
    mlp_stage<128, true, true, false, false>(
        sh0, 128, wl0, P1, P2, bl0, nullptr, sh1, 0, kh, r0, c0);

    // ---- stage 3: out = h0 + relu(h1 @ Wl1 + bl1) ----
    CP_WAIT(0);
    __syncthreads();
    mlp_stage<128, true, true, true, true>(
        sh1, 128, wl1, P1, P2, bl1, sh0, out, row0, kh, r0, c0);
}

// ---------------------------------------------------------------------------
extern "C" void kernel_launch(void* const* d_in, const int* in_sizes, int n_in,
                              void* d_out, int out_size) {
    const float* seqs = (const float*)d_in[0];
    const float* W2   = (const float*)d_in[3];
    const float* p    = (const float*)d_in[6];
    const float* Wq   = (const float*)d_in[7];
    const float* Wl0  = (const float*)d_in[8];
    const float* bl0  = (const float*)d_in[9];
    const float* Wl1  = (const float*)d_in[10];
    const float* bl1  = (const float*)d_in[11];
    float* out = (float*)d_out;

    static bool init_done = false;
    if (!init_done) {
        cudaFuncSetAttribute(mlp_kernel,
                             cudaFuncAttributeMaxDynamicSharedMemorySize, 221184);
        init_done = true;
    }

    attn_kernel<<<NG / 2, 256>>>(seqs, W2, p);
    mlp_kernel<<<NG / 32, 1024, 221184>>>(Wq, Wl0, bl0, Wl1, bl1, out);
}